// round 2
// baseline (speedup 1.0000x reference)
#include <cuda_runtime.h>

#define DIMQ 64
#define H1   128
#define H2   16
#define NC   4
#define VCH  5
#define IMGD 224
#define PP   (IMGD*IMGD)   // 50176
#define BB   32
#define NROWS (BB + BB*NC) // 160

// Scratch for the 16-dim embeddings (q rows 0..31, k rows 32..159)
__device__ float g_emb[NROWS * H2];

// ---------------------------------------------------------------------------
// Kernel A: per-row MLP + LayerNorm. One block per row, 128 threads.
// ---------------------------------------------------------------------------
__global__ void mlp_ln_kernel(
    const float* __restrict__ q,    // (B, 64, 1)
    const float* __restrict__ k,    // (B, 64, 1, 4)
    const float* __restrict__ Wq1, const float* __restrict__ bq1,
    const float* __restrict__ Wq2, const float* __restrict__ bq2,
    const float* __restrict__ gq,  const float* __restrict__ betaq,
    const float* __restrict__ Wk1, const float* __restrict__ bk1,
    const float* __restrict__ Wk2, const float* __restrict__ bk2,
    const float* __restrict__ gk,  const float* __restrict__ betak)
{
    __shared__ float sx[DIMQ];
    __shared__ float sh1[H1];
    __shared__ float sh2[H2];

    const int r   = blockIdx.x;
    const int tid = threadIdx.x;
    const bool isq = (r < BB);

    const float* W1 = isq ? Wq1 : Wk1;
    const float* B1 = isq ? bq1 : bk1;
    const float* W2 = isq ? Wq2 : Wk2;
    const float* B2 = isq ? bq2 : bk2;
    const float* G  = isq ? gq  : gk;
    const float* BE = isq ? betaq : betak;

    if (tid < DIMQ) {
        if (isq) {
            sx[tid] = q[r * DIMQ + tid];
        } else {
            int rr = r - BB;
            int b  = rr >> 2;
            int c  = rr & 3;
            // k layout: (B, DIM, 1, C) -> idx = (b*DIM + d)*C + c
            sx[tid] = k[(b * DIMQ + tid) * NC + c];
        }
    }
    __syncthreads();

    // Layer 1: thread j computes hidden unit j (64 FMAs), then LeakyReLU(0.1)
    {
        float acc = B1[tid];
        #pragma unroll
        for (int d = 0; d < DIMQ; d++)
            acc = fmaf(sx[d], W1[d * H1 + tid], acc);
        sh1[tid] = (acc > 0.0f) ? acc : 0.1f * acc;
    }
    __syncthreads();

    // Layer 2: threads 0..15 compute output unit o (128 FMAs)
    if (tid < H2) {
        float acc = B2[tid];
        #pragma unroll 8
        for (int j = 0; j < H1; j++)
            acc = fmaf(sh1[j], W2[j * H2 + tid], acc);
        sh2[tid] = acc;
    }
    __syncthreads();

    // LayerNorm over 16 (each of the 16 threads redundantly computes mu/var)
    if (tid < H2) {
        float mu = 0.0f;
        #pragma unroll
        for (int o = 0; o < H2; o++) mu += sh2[o];
        mu *= (1.0f / H2);
        float var = 0.0f;
        #pragma unroll
        for (int o = 0; o < H2; o++) {
            float d = sh2[o] - mu;
            var = fmaf(d, d, var);
        }
        var *= (1.0f / H2);
        float y = (sh2[tid] - mu) * rsqrtf(var + 1e-5f) * G[tid] + BE[tid];
        g_emb[r * H2 + tid] = y;
    }
}

// ---------------------------------------------------------------------------
// Kernel B: softmax (per block, recomputed cheaply) + masked renorm + fuse.
// Grid: (PP/256, B), block 256 -> exactly one thread per (b, pixel).
// ---------------------------------------------------------------------------
__global__ void fuse_kernel(
    const float* __restrict__ v,     // (B, VCH, P, C)
    const float* __restrict__ mask,  // (B, 1, IMG, IMG, C) == (B, P, C)
    const int*   __restrict__ md,    // (B, C)
    float*       __restrict__ out)   // [fused (B,VCH,IMG,IMG) | attention (B,C,IMG,IMG)]
{
    __shared__ float s_att[NC];
    const int b = blockIdx.y;

    if (threadIdx.x == 0) {
        const float* qe = &g_emb[b * H2];
        float logit[NC];
        float mx = -1e30f;
        #pragma unroll
        for (int c = 0; c < NC; c++) {
            const float* ke = &g_emb[(BB + b * NC + c) * H2];
            float acc = 0.0f;
            #pragma unroll
            for (int o = 0; o < H2; o++) acc = fmaf(qe[o], ke[o], acc);
            // scale = DIM^-0.5 = 0.125 ; modality dropout ; /TEMPERATURE
            float l = (acc * 0.125f - (float)md[b * NC + c] * 1.0e5f) * 0.1f;
            logit[c] = l;
            mx = fmaxf(mx, l);
        }
        float s = 0.0f;
        #pragma unroll
        for (int c = 0; c < NC; c++) { logit[c] = __expf(logit[c] - mx); s += logit[c]; }
        float inv = 1.0f / s;
        #pragma unroll
        for (int c = 0; c < NC; c++) s_att[c] = logit[c] * inv;
    }
    __syncthreads();

    const float a0 = s_att[0], a1 = s_att[1], a2 = s_att[2], a3 = s_att[3];

    const int p = blockIdx.x * blockDim.x + threadIdx.x;   // PP = 196*256 exactly
    if (p >= PP) return;

    // mask: contiguous in C -> vectorized 16B load
    const float4 m4 = *reinterpret_cast<const float4*>(mask + ((size_t)b * PP + p) * NC);

    float w0 = a0 * m4.x;
    float w1 = a1 * m4.y;
    float w2 = a2 * m4.z;
    float w3 = a3 * m4.w;
    float ssum = w0 + w1 + w2 + w3 + 1e-8f;
    float inv  = 1.0f / ssum;
    w0 *= inv; w1 *= inv; w2 *= inv; w3 *= inv;

    // fused[b, vc, p] = dot(att_norm, v[b, vc, p, :])
    const size_t fbase = (size_t)b * VCH * PP;
    #pragma unroll
    for (int vc = 0; vc < VCH; vc++) {
        const float4 v4 = *reinterpret_cast<const float4*>(
            v + ((size_t)(b * VCH + vc) * PP + p) * NC);
        float f = w0 * v4.x;
        f = fmaf(w1, v4.y, f);
        f = fmaf(w2, v4.z, f);
        f = fmaf(w3, v4.w, f);
        out[fbase + (size_t)vc * PP + p] = f;
    }

    // attention[b, c, p]
    const size_t abase = (size_t)BB * VCH * PP + (size_t)b * NC * PP + p;
    out[abase]            = w0;
    out[abase +     PP]   = w1;
    out[abase + 2 * PP]   = w2;
    out[abase + 3 * PP]   = w3;
}

// ---------------------------------------------------------------------------
// Launch. Input order (metadata): q, k, v, mask, modality_dropout,
// Wq1, bq1, Wq2, bq2, gq, betaq, Wk1, bk1, Wk2, bk2, gk, betak
// ---------------------------------------------------------------------------
extern "C" void kernel_launch(void* const* d_in, const int* in_sizes, int n_in,
                              void* d_out, int out_size)
{
    const float* q     = (const float*)d_in[0];
    const float* k     = (const float*)d_in[1];
    const float* v     = (const float*)d_in[2];
    const float* mask  = (const float*)d_in[3];
    const int*   md    = (const int*)  d_in[4];
    const float* Wq1   = (const float*)d_in[5];
    const float* bq1   = (const float*)d_in[6];
    const float* Wq2   = (const float*)d_in[7];
    const float* bq2   = (const float*)d_in[8];
    const float* gq    = (const float*)d_in[9];
    const float* betaq = (const float*)d_in[10];
    const float* Wk1   = (const float*)d_in[11];
    const float* bk1   = (const float*)d_in[12];
    const float* Wk2   = (const float*)d_in[13];
    const float* bk2   = (const float*)d_in[14];
    const float* gk    = (const float*)d_in[15];
    const float* betak = (const float*)d_in[16];
    float* out = (float*)d_out;

    mlp_ln_kernel<<<NROWS, H1>>>(q, k, Wq1, bq1, Wq2, bq2, gq, betaq,
                                 Wk1, bk1, Wk2, bk2, gk, betak);

    dim3 grid(PP / 256, BB);
    fuse_kernel<<<grid, 256>>>(v, mask, md, out);
}

// round 3
// speedup vs baseline: 1.0769x; 1.0769x over previous
#include <cuda_runtime.h>

#define DIMQ 64
#define H1   128
#define H2   16
#define NC   4
#define VCH  5
#define IMGD 224
#define PP   (IMGD*IMGD)   // 50176
#define BB   32

// Per-batch softmax attention weights (B x 4)
__device__ float g_att[BB * NC];

// ---------------------------------------------------------------------------
// Kernel A: one block per batch. Computes q-embedding + 4 k-embeddings
// (MLP 64->128 leaky -> 128->16 -> LN16), logits, softmax -> g_att[b][0..3].
// 128 threads.
// ---------------------------------------------------------------------------
__global__ void mlp_att_kernel(
    const float* __restrict__ q,    // (B, 64, 1)
    const float* __restrict__ k,    // (B, 64, 1, 4)
    const int*   __restrict__ md,   // (B, 4)
    const float* __restrict__ Wq1, const float* __restrict__ bq1,
    const float* __restrict__ Wq2, const float* __restrict__ bq2,
    const float* __restrict__ gq,  const float* __restrict__ betaq,
    const float* __restrict__ Wk1, const float* __restrict__ bk1,
    const float* __restrict__ Wk2, const float* __restrict__ bk2,
    const float* __restrict__ gk,  const float* __restrict__ betak)
{
    __shared__ float sx[5][DIMQ];     // row 0 = q, rows 1..4 = k contrasts
    __shared__ float sh1[5][H1];
    __shared__ float sh2[5][H2];
    __shared__ float semb[5][H2];
    __shared__ float slog[NC];

    const int b   = blockIdx.x;
    const int tid = threadIdx.x;

    // Load inputs: 5*64 = 320 values
    for (int i = tid; i < 5 * DIMQ; i += H1) {
        int row = i >> 6;
        int d   = i & 63;
        sx[row][d] = (row == 0) ? q[b * DIMQ + d]
                                : k[(b * DIMQ + d) * NC + (row - 1)];
    }
    __syncthreads();

    // Layer 1: 5*128 = 640 hidden units, 5 per thread
    #pragma unroll
    for (int it = 0; it < 5; it++) {
        int u   = it * H1 + tid;
        int row = u >> 7;
        int j   = u & 127;
        const float* W1 = (row == 0) ? Wq1 : Wk1;
        const float* B1 = (row == 0) ? bq1 : bk1;
        float acc = B1[j];
        #pragma unroll
        for (int d = 0; d < DIMQ; d++)
            acc = fmaf(sx[row][d], W1[d * H1 + j], acc);
        sh1[row][j] = (acc > 0.0f) ? acc : 0.1f * acc;
    }
    __syncthreads();

    // Layer 2: 5*16 = 80 output units
    if (tid < 80) {
        int row = tid >> 4;
        int o   = tid & 15;
        const float* W2 = (row == 0) ? Wq2 : Wk2;
        const float* B2 = (row == 0) ? bq2 : bk2;
        float acc = B2[o];
        #pragma unroll 8
        for (int j = 0; j < H1; j++)
            acc = fmaf(sh1[row][j], W2[j * H2 + o], acc);
        sh2[row][o] = acc;
    }
    __syncthreads();

    // LayerNorm(16) per row (redundant mu/var per thread — trivial)
    if (tid < 80) {
        int row = tid >> 4;
        int o   = tid & 15;
        const float* G  = (row == 0) ? gq    : gk;
        const float* BE = (row == 0) ? betaq : betak;
        float mu = 0.0f;
        #pragma unroll
        for (int j = 0; j < H2; j++) mu += sh2[row][j];
        mu *= (1.0f / H2);
        float var = 0.0f;
        #pragma unroll
        for (int j = 0; j < H2; j++) {
            float d = sh2[row][j] - mu;
            var = fmaf(d, d, var);
        }
        var *= (1.0f / H2);
        semb[row][o] = (sh2[row][o] - mu) * rsqrtf(var + 1e-5f) * G[o] + BE[o];
    }
    __syncthreads();

    // Logits: 4 threads, one contrast each
    if (tid < NC) {
        float acc = 0.0f;
        #pragma unroll
        for (int o = 0; o < H2; o++)
            acc = fmaf(semb[0][o], semb[1 + tid][o], acc);
        // scale DIM^-0.5 = 0.125, modality dropout, /TEMPERATURE(10)
        slog[tid] = (acc * 0.125f - (float)md[b * NC + tid] * 1.0e5f) * 0.1f;
    }
    __syncthreads();

    // Softmax: thread 0
    if (tid == 0) {
        float l0 = slog[0], l1 = slog[1], l2 = slog[2], l3 = slog[3];
        float mx = fmaxf(fmaxf(l0, l1), fmaxf(l2, l3));
        float e0 = __expf(l0 - mx), e1 = __expf(l1 - mx),
              e2 = __expf(l2 - mx), e3 = __expf(l3 - mx);
        float inv = 1.0f / (e0 + e1 + e2 + e3);
        g_att[b * NC + 0] = e0 * inv;
        g_att[b * NC + 1] = e1 * inv;
        g_att[b * NC + 2] = e2 * inv;
        g_att[b * NC + 3] = e3 * inv;
    }
}

// ---------------------------------------------------------------------------
// Kernel B: masked renorm + fuse. 4 pixels per thread, all 128-bit LD/ST.
// Grid: (PP/1024, B) x 256 threads. No shared memory, no __syncthreads.
// ---------------------------------------------------------------------------
__global__ void __launch_bounds__(256)
fuse_kernel(
    const float* __restrict__ v,     // (B, VCH, P, C)
    const float* __restrict__ mask,  // (B, P, C)
    float*       __restrict__ out)   // [fused (B,VCH,P) | attention (B,C,P)]
{
    const int b  = blockIdx.y;
    const int p0 = (blockIdx.x * 256 + threadIdx.x) * 4;   // 4 consecutive pixels

    const float4 att = *reinterpret_cast<const float4*>(&g_att[b * NC]);

    // Load 4 pixels' masks (64B contiguous per thread)
    const float4* mp = reinterpret_cast<const float4*>(mask + ((size_t)b * PP + p0) * NC);
    float w[4][4];
    #pragma unroll
    for (int px = 0; px < 4; px++) {
        float4 m = mp[px];
        float w0 = att.x * m.x;
        float w1 = att.y * m.y;
        float w2 = att.z * m.z;
        float w3 = att.w * m.w;
        float inv = 1.0f / (w0 + w1 + w2 + w3 + 1e-8f);
        w[px][0] = w0 * inv;
        w[px][1] = w1 * inv;
        w[px][2] = w2 * inv;
        w[px][3] = w3 * inv;
    }

    // Fused output: 5 channels, float4 store each
    const size_t fbase = (size_t)b * VCH * PP;
    #pragma unroll
    for (int vc = 0; vc < VCH; vc++) {
        const float4* vp = reinterpret_cast<const float4*>(
            v + ((size_t)(b * VCH + vc) * PP + p0) * NC);
        float4 f;
        {
            float4 x = vp[0];
            f.x = fmaf(w[0][3], x.w, fmaf(w[0][2], x.z, fmaf(w[0][1], x.y, w[0][0] * x.x)));
        }
        {
            float4 x = vp[1];
            f.y = fmaf(w[1][3], x.w, fmaf(w[1][2], x.z, fmaf(w[1][1], x.y, w[1][0] * x.x)));
        }
        {
            float4 x = vp[2];
            f.z = fmaf(w[2][3], x.w, fmaf(w[2][2], x.z, fmaf(w[2][1], x.y, w[2][0] * x.x)));
        }
        {
            float4 x = vp[3];
            f.w = fmaf(w[3][3], x.w, fmaf(w[3][2], x.z, fmaf(w[3][1], x.y, w[3][0] * x.x)));
        }
        *reinterpret_cast<float4*>(out + fbase + (size_t)vc * PP + p0) = f;
    }

    // Attention output: 4 contrast planes, float4 store each
    const size_t abase = (size_t)BB * VCH * PP + (size_t)b * NC * PP + p0;
    #pragma unroll
    for (int c = 0; c < NC; c++) {
        float4 a;
        a.x = w[0][c]; a.y = w[1][c]; a.z = w[2][c]; a.w = w[3][c];
        *reinterpret_cast<float4*>(out + abase + (size_t)c * PP) = a;
    }
}

// ---------------------------------------------------------------------------
// Launch. Input order: q, k, v, mask, modality_dropout,
// Wq1, bq1, Wq2, bq2, gq, betaq, Wk1, bk1, Wk2, bk2, gk, betak
// ---------------------------------------------------------------------------
extern "C" void kernel_launch(void* const* d_in, const int* in_sizes, int n_in,
                              void* d_out, int out_size)
{
    const float* q     = (const float*)d_in[0];
    const float* k     = (const float*)d_in[1];
    const float* v     = (const float*)d_in[2];
    const float* mask  = (const float*)d_in[3];
    const int*   md    = (const int*)  d_in[4];
    const float* Wq1   = (const float*)d_in[5];
    const float* bq1   = (const float*)d_in[6];
    const float* Wq2   = (const float*)d_in[7];
    const float* bq2   = (const float*)d_in[8];
    const float* gq    = (const float*)d_in[9];
    const float* betaq = (const float*)d_in[10];
    const float* Wk1   = (const float*)d_in[11];
    const float* bk1   = (const float*)d_in[12];
    const float* Wk2   = (const float*)d_in[13];
    const float* bk2   = (const float*)d_in[14];
    const float* gk    = (const float*)d_in[15];
    const float* betak = (const float*)d_in[16];
    float* out = (float*)d_out;

    mlp_att_kernel<<<BB, 128>>>(q, k, md,
                                Wq1, bq1, Wq2, bq2, gq, betaq,
                                Wk1, bk1, Wk2, bk2, gk, betak);

    dim3 grid(PP / 1024, BB);   // 49 x 32 blocks, 256 threads, 4 px/thread
    fuse_kernel<<<grid, 256>>>(v, mask, out);
}

// round 4
// speedup vs baseline: 1.1898x; 1.1048x over previous
#include <cuda_runtime.h>

#define DIMQ 64
#define H1   128
#define H2   16
#define NC   4
#define VCH  5
#define IMGD 224
#define PP   (IMGD*IMGD)   // 50176
#define BB   32

// Per-batch softmax attention weights (B x 4)
__device__ float g_att[BB * NC];

// Dynamic smem layout (floats):
//  sWq1: 8192 | sWk1: 8192 | sWq2: 2048 | sWk2: 2048
//  sx: 320 | sh1: 640 | sh2p: 160 | sh2: 80 | semb: 80 | slog: 4
#define OFF_WQ1 0
#define OFF_WK1 (OFF_WQ1 + 8192)
#define OFF_WQ2 (OFF_WK1 + 8192)
#define OFF_WK2 (OFF_WQ2 + 2048)
#define OFF_X   (OFF_WK2 + 2048)
#define OFF_H1  (OFF_X   + 320)
#define OFF_H2P (OFF_H1  + 640)
#define OFF_H2  (OFF_H2P + 160)
#define OFF_EMB (OFF_H2  + 80)
#define OFF_LOG (OFF_EMB + 80)
#define SMEM_FLOATS (OFF_LOG + 4)
#define SMEM_BYTES  (SMEM_FLOATS * 4)

// ---------------------------------------------------------------------------
// Kernel A: one block per batch, 256 threads. Stage all weights in smem with
// coalesced float4 loads (high MLP, single latency round-trip), then compute
// q-embedding + 4 k-embeddings, logits, softmax -> g_att.
// ---------------------------------------------------------------------------
__global__ void __launch_bounds__(256)
mlp_att_kernel(
    const float* __restrict__ q,    // (B, 64, 1)
    const float* __restrict__ k,    // (B, 64, 1, 4)
    const int*   __restrict__ md,   // (B, 4)
    const float* __restrict__ Wq1, const float* __restrict__ bq1,
    const float* __restrict__ Wq2, const float* __restrict__ bq2,
    const float* __restrict__ gq,  const float* __restrict__ betaq,
    const float* __restrict__ Wk1, const float* __restrict__ bk1,
    const float* __restrict__ Wk2, const float* __restrict__ bk2,
    const float* __restrict__ gk,  const float* __restrict__ betak)
{
    extern __shared__ float sm[];
    const int b   = blockIdx.x;
    const int tid = threadIdx.x;

    // ---- Stage weights: all float4, fully independent loads ----
    {
        float4*       dW1q = reinterpret_cast<float4*>(sm + OFF_WQ1);
        float4*       dW1k = reinterpret_cast<float4*>(sm + OFF_WK1);
        const float4* sW1q = reinterpret_cast<const float4*>(Wq1);
        const float4* sW1k = reinterpret_cast<const float4*>(Wk1);
        #pragma unroll
        for (int i = 0; i < 8; i++) {               // 2048 float4 each
            dW1q[tid + i * 256] = sW1q[tid + i * 256];
            dW1k[tid + i * 256] = sW1k[tid + i * 256];
        }
        float4*       dW2q = reinterpret_cast<float4*>(sm + OFF_WQ2);
        float4*       dW2k = reinterpret_cast<float4*>(sm + OFF_WK2);
        const float4* sW2q = reinterpret_cast<const float4*>(Wq2);
        const float4* sW2k = reinterpret_cast<const float4*>(Wk2);
        #pragma unroll
        for (int i = 0; i < 2; i++) {               // 512 float4 each
            dW2q[tid + i * 256] = sW2q[tid + i * 256];
            dW2k[tid + i * 256] = sW2k[tid + i * 256];
        }
    }

    // ---- Stage inputs: 5*64 = 320 values (row 0 = q, rows 1..4 = k) ----
    for (int i = tid; i < 5 * DIMQ; i += 256) {
        int row = i >> 6;
        int d   = i & 63;
        sm[OFF_X + i] = (row == 0) ? q[b * DIMQ + d]
                                   : k[(b * DIMQ + d) * NC + (row - 1)];
    }
    __syncthreads();

    // ---- Layer 1: 640 units over 256 threads (<=3 each), from smem ----
    #pragma unroll
    for (int it = 0; it < 3; it++) {
        int u = tid + it * 256;
        if (u < 640) {
            int row = u >> 7;           // 0..4
            int j   = u & 127;
            const float* W1 = (row == 0) ? (sm + OFF_WQ1) : (sm + OFF_WK1);
            const float* B1 = (row == 0) ? bq1 : bk1;
            const float* x  = sm + OFF_X + row * DIMQ;
            float acc = B1[j];
            #pragma unroll
            for (int d = 0; d < DIMQ; d++)
                acc = fmaf(x[d], W1[d * H1 + j], acc);
            sm[OFF_H1 + row * H1 + j] = (acc > 0.0f) ? acc : 0.1f * acc;
        }
    }
    __syncthreads();

    // ---- Layer 2: 80 units, split-K over 2 halves (160 threads active) ----
    if (tid < 160) {
        int idx  = tid % 80;
        int half = tid / 80;            // 0: j=0..63, 1: j=64..127
        int row  = idx >> 4;
        int o    = idx & 15;
        const float* W2 = (row == 0) ? (sm + OFF_WQ2) : (sm + OFF_WK2);
        const float* B2 = (row == 0) ? bq2 : bk2;
        const float* h  = sm + OFF_H1 + row * H1 + half * 64;
        const float* w  = W2 + half * 64 * H2;
        float acc = (half == 0) ? B2[o] : 0.0f;
        #pragma unroll
        for (int j = 0; j < 64; j++)
            acc = fmaf(h[j], w[j * H2 + o], acc);
        sm[OFF_H2P + half * 80 + idx] = acc;
    }
    __syncthreads();

    if (tid < 80)
        sm[OFF_H2 + tid] = sm[OFF_H2P + tid] + sm[OFF_H2P + 80 + tid];
    __syncthreads();

    // ---- LayerNorm(16) per row ----
    if (tid < 80) {
        int row = tid >> 4;
        int o   = tid & 15;
        const float* G  = (row == 0) ? gq    : gk;
        const float* BE = (row == 0) ? betaq : betak;
        const float* h2 = sm + OFF_H2 + row * H2;
        float mu = 0.0f;
        #pragma unroll
        for (int j = 0; j < H2; j++) mu += h2[j];
        mu *= (1.0f / H2);
        float var = 0.0f;
        #pragma unroll
        for (int j = 0; j < H2; j++) {
            float d = h2[j] - mu;
            var = fmaf(d, d, var);
        }
        var *= (1.0f / H2);
        sm[OFF_EMB + tid] = (h2[o] - mu) * rsqrtf(var + 1e-5f) * G[o] + BE[o];
    }
    __syncthreads();

    // ---- Logits ----
    if (tid < NC) {
        float acc = 0.0f;
        #pragma unroll
        for (int o = 0; o < H2; o++)
            acc = fmaf(sm[OFF_EMB + o], sm[OFF_EMB + (1 + tid) * H2 + o], acc);
        // scale DIM^-0.5 = 0.125, modality dropout, /TEMPERATURE(10)
        sm[OFF_LOG + tid] = (acc * 0.125f - (float)md[b * NC + tid] * 1.0e5f) * 0.1f;
    }
    __syncthreads();

    // ---- Softmax -> g_att ----
    if (tid == 0) {
        float l0 = sm[OFF_LOG + 0], l1 = sm[OFF_LOG + 1],
              l2 = sm[OFF_LOG + 2], l3 = sm[OFF_LOG + 3];
        float mx = fmaxf(fmaxf(l0, l1), fmaxf(l2, l3));
        float e0 = __expf(l0 - mx), e1 = __expf(l1 - mx),
              e2 = __expf(l2 - mx), e3 = __expf(l3 - mx);
        float inv = 1.0f / (e0 + e1 + e2 + e3);
        g_att[b * NC + 0] = e0 * inv;
        g_att[b * NC + 1] = e1 * inv;
        g_att[b * NC + 2] = e2 * inv;
        g_att[b * NC + 3] = e3 * inv;
    }
}

// ---------------------------------------------------------------------------
// Kernel B: masked renorm + fuse. 4 pixels per thread, all 128-bit LD/ST.
// Grid: (PP/1024, B) x 256 threads. (unchanged from R2 — 33.8us, 69% DRAM)
// ---------------------------------------------------------------------------
__global__ void __launch_bounds__(256)
fuse_kernel(
    const float* __restrict__ v,     // (B, VCH, P, C)
    const float* __restrict__ mask,  // (B, P, C)
    float*       __restrict__ out)   // [fused (B,VCH,P) | attention (B,C,P)]
{
    const int b  = blockIdx.y;
    const int p0 = (blockIdx.x * 256 + threadIdx.x) * 4;   // 4 consecutive pixels

    const float4 att = *reinterpret_cast<const float4*>(&g_att[b * NC]);

    const float4* mp = reinterpret_cast<const float4*>(mask + ((size_t)b * PP + p0) * NC);
    float w[4][4];
    #pragma unroll
    for (int px = 0; px < 4; px++) {
        float4 m = mp[px];
        float w0 = att.x * m.x;
        float w1 = att.y * m.y;
        float w2 = att.z * m.z;
        float w3 = att.w * m.w;
        float inv = 1.0f / (w0 + w1 + w2 + w3 + 1e-8f);
        w[px][0] = w0 * inv;
        w[px][1] = w1 * inv;
        w[px][2] = w2 * inv;
        w[px][3] = w3 * inv;
    }

    const size_t fbase = (size_t)b * VCH * PP;
    #pragma unroll
    for (int vc = 0; vc < VCH; vc++) {
        const float4* vp = reinterpret_cast<const float4*>(
            v + ((size_t)(b * VCH + vc) * PP + p0) * NC);
        float4 f;
        {
            float4 x = vp[0];
            f.x = fmaf(w[0][3], x.w, fmaf(w[0][2], x.z, fmaf(w[0][1], x.y, w[0][0] * x.x)));
        }
        {
            float4 x = vp[1];
            f.y = fmaf(w[1][3], x.w, fmaf(w[1][2], x.z, fmaf(w[1][1], x.y, w[1][0] * x.x)));
        }
        {
            float4 x = vp[2];
            f.z = fmaf(w[2][3], x.w, fmaf(w[2][2], x.z, fmaf(w[2][1], x.y, w[2][0] * x.x)));
        }
        {
            float4 x = vp[3];
            f.w = fmaf(w[3][3], x.w, fmaf(w[3][2], x.z, fmaf(w[3][1], x.y, w[3][0] * x.x)));
        }
        *reinterpret_cast<float4*>(out + fbase + (size_t)vc * PP + p0) = f;
    }

    const size_t abase = (size_t)BB * VCH * PP + (size_t)b * NC * PP + p0;
    #pragma unroll
    for (int c = 0; c < NC; c++) {
        float4 a;
        a.x = w[0][c]; a.y = w[1][c]; a.z = w[2][c]; a.w = w[3][c];
        *reinterpret_cast<float4*>(out + abase + (size_t)c * PP) = a;
    }
}

// ---------------------------------------------------------------------------
// Launch. Input order: q, k, v, mask, modality_dropout,
// Wq1, bq1, Wq2, bq2, gq, betaq, Wk1, bk1, Wk2, bk2, gk, betak
// ---------------------------------------------------------------------------
extern "C" void kernel_launch(void* const* d_in, const int* in_sizes, int n_in,
                              void* d_out, int out_size)
{
    const float* q     = (const float*)d_in[0];
    const float* k     = (const float*)d_in[1];
    const float* v     = (const float*)d_in[2];
    const float* mask  = (const float*)d_in[3];
    const int*   md    = (const int*)  d_in[4];
    const float* Wq1   = (const float*)d_in[5];
    const float* bq1   = (const float*)d_in[6];
    const float* Wq2   = (const float*)d_in[7];
    const float* bq2   = (const float*)d_in[8];
    const float* gq    = (const float*)d_in[9];
    const float* betaq = (const float*)d_in[10];
    const float* Wk1   = (const float*)d_in[11];
    const float* bk1   = (const float*)d_in[12];
    const float* Wk2   = (const float*)d_in[13];
    const float* bk2   = (const float*)d_in[14];
    const float* gk    = (const float*)d_in[15];
    const float* betak = (const float*)d_in[16];
    float* out = (float*)d_out;

    static bool attr_set = false;
    if (!attr_set) {
        cudaFuncSetAttribute(mlp_att_kernel,
                             cudaFuncAttributeMaxDynamicSharedMemorySize,
                             SMEM_BYTES);
        attr_set = true;
    }

    mlp_att_kernel<<<BB, 256, SMEM_BYTES>>>(q, k, md,
                                            Wq1, bq1, Wq2, bq2, gq, betaq,
                                            Wk1, bk1, Wk2, bk2, gk, betak);

    dim3 grid(PP / 1024, BB);   // 49 x 32 blocks, 256 threads, 4 px/thread
    fuse_kernel<<<grid, 256>>>(v, mask, out);
}